// round 9
// baseline (speedup 1.0000x reference)
#include <cuda_runtime.h>
#include <cuda_fp16.h>
#include <cstdint>

#define N_NODES 4096
#define FEA 128
#define KD 4096
#define SPLITS 4
#define KSPL (KD / SPLITS)       // 1024
#define BK 64                    // k per tile (128B fp16 rows)
#define TILES (KSPL / BK)        // 16

// ---------------- device scratch (no allocations allowed) -------------------
__device__ __half g_b_hi[(size_t)FEA * N_NODES];  // out1^T hi  [f][node]
__device__ __half g_b_lo[(size_t)FEA * N_NODES];  // out1^T lo
__device__ float g_part[SPLITS][(size_t)N_NODES * FEA];  // split-K partials

// ---------------- helpers ----------------------------------------------------
__device__ __forceinline__ uint32_t smem_u32(const void* p) {
    uint32_t a;
    asm("{ .reg .u64 t; cvta.to.shared.u64 t, %1; cvt.u32.u64 %0, t; }"
        : "=r"(a) : "l"(p));
    return a;
}
__device__ __forceinline__ void ldsm4(uint32_t* r, uint32_t addr) {
    asm volatile("ldmatrix.sync.aligned.m8n8.x4.shared.b16 {%0,%1,%2,%3}, [%4];"
                 : "=r"(r[0]), "=r"(r[1]), "=r"(r[2]), "=r"(r[3]) : "r"(addr));
}
__device__ __forceinline__ void mma16816(float* c, const uint32_t* a,
                                         const uint32_t* b) {
    asm volatile(
        "mma.sync.aligned.m16n8k16.row.col.f32.f16.f16.f32 "
        "{%0,%1,%2,%3}, {%4,%5,%6,%7}, {%8,%9}, {%0,%1,%2,%3};"
        : "+f"(c[0]), "+f"(c[1]), "+f"(c[2]), "+f"(c[3])
        : "r"(a[0]), "r"(a[1]), "r"(a[2]), "r"(a[3]), "r"(b[0]), "r"(b[1]));
}
__device__ __forceinline__ void cp16(uint32_t dst, const void* src) {
    asm volatile("cp.async.cg.shared.global [%0], [%1], 16;"
                 :: "r"(dst), "l"(src) : "memory");
}
__device__ __forceinline__ void cp_commit() {
    asm volatile("cp.async.commit_group;" ::: "memory");
}
__device__ __forceinline__ void cp_wait0() {
    asm volatile("cp.async.wait_group 0;" ::: "memory");
}

#define SWZ(o) ((uint32_t)(o) ^ ((((uint32_t)(o)) >> 3) & 0x70u))

__device__ __forceinline__ uint32_t h2_pack(__half a, __half b) {
    __half2 v; v.x = a; v.y = b;
    return *reinterpret_cast<uint32_t*>(&v);
}

// ---------------------------------------------------------------------------
// Kernel 1: per-node  support = x_n @ W_n, then out1_n = R_n @ support.
// Processes nodes [node0, node0+1024). Plain float4 loads (no __ldcs).
// Emits out1 TRANSPOSED as fp16 (hi, lo): B[f][node], K-major for the GEMM.
// ---------------------------------------------------------------------------
__global__ __launch_bounds__(128) void node_transform_kernel(
    const float* __restrict__ input,   // [N, 128]
    const float* __restrict__ rel,     // [N, 128, 128]
    const float* __restrict__ W,       // [N, 128, 128]
    int node0)
{
    const int n = node0 + blockIdx.x;
    const int t = threadIdx.x;

    __shared__ float in_row[FEA];
    __shared__ float s_vec[FEA];
    __shared__ float partf[4][FEA];

    in_row[t] = input[(size_t)n * FEA + t];
    __syncthreads();

    // ---- phase 1: support = x @ W, vectorized (LDG.128).
    {
        const int q = t & 31, g = t >> 5;
        const float* __restrict__ Wn = W + (size_t)n * FEA * FEA;
        float4 acc4 = make_float4(0.f, 0.f, 0.f, 0.f);
#pragma unroll 8
        for (int jj = 0; jj < 32; ++jj) {
            const int j = g * 32 + jj;
            const float4 w4 = *reinterpret_cast<const float4*>(
                &Wn[(size_t)j * FEA + 4 * q]);
            const float x = in_row[j];
            acc4.x += x * w4.x; acc4.y += x * w4.y;
            acc4.z += x * w4.z; acc4.w += x * w4.w;
        }
        *reinterpret_cast<float4*>(&partf[g][4 * q]) = acc4;
        __syncthreads();
        s_vec[t] = partf[0][t] + partf[1][t] + partf[2][t] + partf[3][t];
        __syncthreads();
    }

    // ---- phase 2: out1[j] = sum_k R[j,k] * s[k]
    const int w = t >> 5;
    const int l = t & 31;
    const float4 s4 = *reinterpret_cast<const float4*>(&s_vec[4 * l]);
    const float* __restrict__ Rn = rel + (size_t)n * FEA * FEA;

#pragma unroll 4
    for (int jj = 0; jj < 32; ++jj) {
        const int j = w * 32 + jj;
        const float4 r4 = *reinterpret_cast<const float4*>(&Rn[(size_t)j * FEA + 4 * l]);
        float p = r4.x * s4.x + r4.y * s4.y + r4.z * s4.z + r4.w * s4.w;
#pragma unroll
        for (int off = 16; off > 0; off >>= 1)
            p += __shfl_xor_sync(0xffffffffu, p, off);
        if (l == jj) {
            const __half h = __float2half_rn(p);
            const float  r = p - __half2float(h);
            g_b_hi[(size_t)j * N_NODES + n] = h;
            g_b_lo[(size_t)j * N_NODES + n] = __float2half_rn(r);
        }
    }
}

// ---------------------------------------------------------------------------
// Kernel 2: one split of the split-K HMMA GEMM (runs concurrently with the
// transform kernel working on later splits).
// partial[s] = adj[:, sK:(s+1)K] @ out1[sK:(s+1)K, :]
// CTA tile 128x128, BK=64, double-buffered smem, 8 warps (4M x 2N).
// adj as single fp16 (rel err 2^-11), out1 as fp16 hi/lo -> 2 MMA per frag.
// ---------------------------------------------------------------------------
#define TILE_B 16384                        // one operand tile: 128 x 64 fp16
#define BUF_B (3 * TILE_B)                  // A, B_hi, B_lo
#define SMEM_REQ (2 * BUF_B + 1024)

__global__ __launch_bounds__(256, 1) void hmma_gemm_kernel(
    const float* __restrict__ A, int split)
{
    extern __shared__ char dsm[];
    const uint32_t raw  = smem_u32(dsm);
    const uint32_t base = (raw + 1023u) & ~1023u;
    char* smb = dsm + (base - raw);

    const int t   = threadIdx.x;
    const int wid = t >> 5;
    const int l   = t & 31;
    const int m0  = blockIdx.x * 128;
    const int kb0 = split * KSPL;

    const int warpM = wid & 3;   // 0..3 -> 32 rows each
    const int warpN = wid >> 2;  // 0..1 -> 64 cols each

    // ---- per-lane ldmatrix address components ----
    uint32_t aRowOff[2], aXor[2];
#pragma unroll
    for (int mf = 0; mf < 2; ++mf) {
        const int r = warpM * 32 + mf * 16 + (l & 15);
        aRowOff[mf] = r * 128;
        aXor[mf]    = (r & 7) * 16;
    }
    const uint32_t aK = (l >> 4) * 16;
    uint32_t bRowOff[4], bXor[4];
#pragma unroll
    for (int q = 0; q < 4; ++q) {
        const int r = warpN * 64 + q * 16 + ((l >> 4) << 3) + (l & 7);
        bRowOff[q] = r * 128;
        bXor[q]    = (r & 7) * 16;
    }
    const uint32_t bK = ((l >> 3) & 1) * 16;

    // ---- staging maps ----
    const int aRow = t >> 1;                 // A: 128 rows, 2 threads/row
    const int aC4  = (t & 1) * 8;            // float4 idx, 8 per thread
    const int bRow = t >> 1;
    const int bC   = (t & 1) * 4;

    float c[2][8][4];
#pragma unroll
    for (int i = 0; i < 2; ++i)
#pragma unroll
        for (int j = 0; j < 8; ++j)
#pragma unroll
            for (int k = 0; k < 4; ++k) c[i][j][k] = 0.0f;

    float4 aPre[8];

    // convert aPre -> single fp16 A tile at smem byte offset `dst`
    auto convert_store = [&](uint32_t dst) {
#pragma unroll
        for (int r = 0; r < 8; ++r) {
            const float4 v = aPre[r];
            uint2 hv;
            hv.x = h2_pack(__float2half_rn(v.x), __float2half_rn(v.y));
            hv.y = h2_pack(__float2half_rn(v.z), __float2half_rn(v.w));
            const uint32_t off = SWZ(aRow * 128 + (aC4 + r) * 8);
            *reinterpret_cast<uint2*>(smb + dst + off) = hv;
        }
    };

    // one k16 compute step on buffer at byte offset `cur`
    auto compute_step = [&](uint32_t cur, int st) {
        const uint32_t aB  = base + cur;
        const uint32_t bHb = aB + TILE_B;
        const uint32_t bLb = aB + 2 * TILE_B;
        const uint32_t k2 = st * 32;
        uint32_t ah[2][4];
#pragma unroll
        for (int mf = 0; mf < 2; ++mf)
            ldsm4(ah[mf], aB + aRowOff[mf] + ((aK + k2) ^ aXor[mf]));
        uint32_t bh[4][4], bl[4][4];
#pragma unroll
        for (int q = 0; q < 4; ++q) {
            const uint32_t off = bRowOff[q] + ((bK + k2) ^ bXor[q]);
            ldsm4(bh[q], bHb + off);
            ldsm4(bl[q], bLb + off);
        }
#pragma unroll
        for (int mf = 0; mf < 2; ++mf)
#pragma unroll
            for (int q = 0; q < 4; ++q)
#pragma unroll
                for (int h = 0; h < 2; ++h) {
                    float* cc = c[mf][2 * q + h];
                    mma16816(cc, ah[mf], &bh[q][2 * h]);
                    mma16816(cc, ah[mf], &bl[q][2 * h]);
                }
    };

    // ================== prologue: stage tile 0 into buffer 0 =================
    {
#pragma unroll
        for (int r = 0; r < 4; ++r) {
            const uint32_t dof = SWZ(bRow * 128 + (bC + r) * 16);
            const size_t   src = (size_t)bRow * KD + kb0 + (bC + r) * 8;
            cp16(base + TILE_B + dof, &g_b_hi[src]);
            cp16(base + 2 * TILE_B + dof, &g_b_lo[src]);
        }
        cp_commit();
#pragma unroll
        for (int r = 0; r < 8; ++r)
            aPre[r] = *reinterpret_cast<const float4*>(
                &A[(size_t)(m0 + aRow) * KD + kb0 + ((aC4 + r) << 2)]);
        convert_store(0);
        cp_wait0();
        __syncthreads();
    }

    // ================== main loop =============================================
    for (int kt = 0; kt < TILES; ++kt) {
        const uint32_t cur = (kt & 1) * BUF_B;
        const uint32_t nxt = cur ^ BUF_B;
        const bool have_next = (kt + 1) < TILES;

        if (have_next) {
            const int kb = kb0 + (kt + 1) * BK;
#pragma unroll
            for (int r = 0; r < 4; ++r) {
                const uint32_t dof = SWZ(bRow * 128 + (bC + r) * 16);
                const size_t   src = (size_t)bRow * KD + kb + (bC + r) * 8;
                cp16(base + nxt + TILE_B + dof, &g_b_hi[src]);
                cp16(base + nxt + 2 * TILE_B + dof, &g_b_lo[src]);
            }
            cp_commit();
#pragma unroll
            for (int r = 0; r < 8; ++r)
                aPre[r] = *reinterpret_cast<const float4*>(
                    &A[(size_t)(m0 + aRow) * KD + kb + ((aC4 + r) << 2)]);
        }

        compute_step(cur, 0);
        compute_step(cur, 1);
        if (have_next) convert_store(nxt);   // overlapped with MMA halves
        compute_step(cur, 2);
        compute_step(cur, 3);

        if (have_next) {
            cp_wait0();
            __syncthreads();
        }
    }

    // ---- epilogue: plain coalesced fp32 partial stores ----
    float* __restrict__ part = g_part[split];
    const int cRow = (l >> 2);
    const int cCol = (l & 3) * 2;
#pragma unroll
    for (int mf = 0; mf < 2; ++mf) {
        const int rbase = m0 + warpM * 32 + mf * 16 + cRow;
#pragma unroll
        for (int nf = 0; nf < 8; ++nf) {
            const int col = warpN * 64 + nf * 8 + cCol;
            float2 v0; v0.x = c[mf][nf][0]; v0.y = c[mf][nf][1];
            float2 v1; v1.x = c[mf][nf][2]; v1.y = c[mf][nf][3];
            *reinterpret_cast<float2*>(&part[(size_t)rbase * FEA + col])       = v0;
            *reinterpret_cast<float2*>(&part[(size_t)(rbase + 8) * FEA + col]) = v1;
        }
    }
}

// ---------------------------------------------------------------------------
// Kernel 3: sum 4 split-K partials + bias.
// ---------------------------------------------------------------------------
__global__ __launch_bounds__(256) void reduce_kernel(
    const float* __restrict__ bias, float* __restrict__ out)
{
    const int i = blockIdx.x * 256 + threadIdx.x;  // float4 index
    const float4 a = reinterpret_cast<const float4*>(g_part[0])[i];
    const float4 b = reinterpret_cast<const float4*>(g_part[1])[i];
    const float4 c = reinterpret_cast<const float4*>(g_part[2])[i];
    const float4 d = reinterpret_cast<const float4*>(g_part[3])[i];
    const float4 bi = *reinterpret_cast<const float4*>(&bias[(i & 31) << 2]);
    float4 o;
    o.x = a.x + b.x + c.x + d.x + bi.x;
    o.y = a.y + b.y + c.y + d.y + bi.y;
    o.z = a.z + b.z + c.z + d.z + bi.z;
    o.w = a.w + b.w + c.w + d.w + bi.w;
    reinterpret_cast<float4*>(out)[i] = o;
}

extern "C" void kernel_launch(void* const* d_in, const int* in_sizes, int n_in,
                              void* d_out, int out_size)
{
    const float* input = (const float*)d_in[0];  // [4096, 128]
    const float* adj   = (const float*)d_in[1];  // [4096, 4096]
    const float* rel   = (const float*)d_in[2];  // [4096, 128, 128]
    const float* W     = (const float*)d_in[3];  // [4096, 128, 128]
    const float* bias  = (const float*)d_in[4];  // [128]
    float* out = (float*)d_out;                  // [4096, 128]

    cudaFuncSetAttribute(hmma_gemm_kernel,
                         cudaFuncAttributeMaxDynamicSharedMemorySize, SMEM_REQ);

    // Fork-join: transform parts on the default stream; each GEMM split runs
    // on a worker stream as soon as its transform part is done, overlapping
    // the (DRAM-bound) transform with the (tensor-bound) GEMM.
    // Host-side stream/event objects only — no device allocations.
    cudaStream_t gs;
    cudaStreamCreateWithFlags(&gs, cudaStreamNonBlocking);
    cudaEvent_t ev[SPLITS], evj;
    for (int s = 0; s < SPLITS; ++s)
        cudaEventCreateWithFlags(&ev[s], cudaEventDisableTiming);
    cudaEventCreateWithFlags(&evj, cudaEventDisableTiming);

    for (int s = 0; s < SPLITS; ++s) {
        node_transform_kernel<<<KSPL, 128, 0, 0>>>(input, rel, W, s * KSPL);
        cudaEventRecord(ev[s], 0);
        cudaStreamWaitEvent(gs, ev[s], 0);
        hmma_gemm_kernel<<<32, 256, SMEM_REQ, gs>>>(adj, s);
    }
    cudaEventRecord(evj, gs);
    cudaStreamWaitEvent(0, evj, 0);
    reduce_kernel<<<(N_NODES * FEA / 4) / 256, 256, 0, 0>>>(bias, out);
}

// round 10
// speedup vs baseline: 1.9812x; 1.9812x over previous
#include <cuda_runtime.h>
#include <cuda_fp16.h>
#include <cstdint>

#define N_NODES 4096
#define FEA 128
#define KD 4096
#define SPLITS 4
#define KSPL (KD / SPLITS)       // 1024
#define BK 64                    // k per tile (128B fp16 rows)
#define TILES (KSPL / BK)        // 16

// ---------------- device scratch (no allocations allowed) -------------------
__device__ __half g_b_hi[(size_t)FEA * N_NODES];  // out1^T hi  [f][node]
__device__ __half g_b_lo[(size_t)FEA * N_NODES];  // out1^T lo
__device__ float g_part[SPLITS][(size_t)N_NODES * FEA];  // split-K partials

// ---------------- helpers ----------------------------------------------------
__device__ __forceinline__ uint32_t smem_u32(const void* p) {
    uint32_t a;
    asm("{ .reg .u64 t; cvta.to.shared.u64 t, %1; cvt.u32.u64 %0, t; }"
        : "=r"(a) : "l"(p));
    return a;
}
__device__ __forceinline__ void ldsm4(uint32_t* r, uint32_t addr) {
    asm volatile("ldmatrix.sync.aligned.m8n8.x4.shared.b16 {%0,%1,%2,%3}, [%4];"
                 : "=r"(r[0]), "=r"(r[1]), "=r"(r[2]), "=r"(r[3]) : "r"(addr));
}
__device__ __forceinline__ void mma16816(float* c, const uint32_t* a,
                                         const uint32_t* b) {
    asm volatile(
        "mma.sync.aligned.m16n8k16.row.col.f32.f16.f16.f32 "
        "{%0,%1,%2,%3}, {%4,%5,%6,%7}, {%8,%9}, {%0,%1,%2,%3};"
        : "+f"(c[0]), "+f"(c[1]), "+f"(c[2]), "+f"(c[3])
        : "r"(a[0]), "r"(a[1]), "r"(a[2]), "r"(a[3]), "r"(b[0]), "r"(b[1]));
}
__device__ __forceinline__ void cp16(uint32_t dst, const void* src) {
    asm volatile("cp.async.cg.shared.global [%0], [%1], 16;"
                 :: "r"(dst), "l"(src) : "memory");
}
__device__ __forceinline__ void cp_commit() {
    asm volatile("cp.async.commit_group;" ::: "memory");
}
__device__ __forceinline__ void cp_wait0() {
    asm volatile("cp.async.wait_group 0;" ::: "memory");
}

#define SWZ(o) ((uint32_t)(o) ^ ((((uint32_t)(o)) >> 3) & 0x70u))

__device__ __forceinline__ uint32_t h2_pack(__half a, __half b) {
    __half2 v; v.x = a; v.y = b;
    return *reinterpret_cast<uint32_t*>(&v);
}

// ---------------------------------------------------------------------------
// Kernel 1: per-node  support = x_n @ W_n, then out1_n = R_n @ support.
// Plain float4 loads (no __ldcs). Emits out1 TRANSPOSED as fp16 (hi, lo).
// ---------------------------------------------------------------------------
__global__ __launch_bounds__(128) void node_transform_kernel(
    const float* __restrict__ input,   // [N, 128]
    const float* __restrict__ rel,     // [N, 128, 128]
    const float* __restrict__ W)       // [N, 128, 128]
{
    const int n = blockIdx.x;
    const int t = threadIdx.x;

    __shared__ float in_row[FEA];
    __shared__ float s_vec[FEA];
    __shared__ float partf[4][FEA];

    in_row[t] = input[(size_t)n * FEA + t];
    __syncthreads();

    // ---- phase 1: support = x @ W, vectorized (LDG.128).
    {
        const int q = t & 31, g = t >> 5;
        const float* __restrict__ Wn = W + (size_t)n * FEA * FEA;
        float4 acc4 = make_float4(0.f, 0.f, 0.f, 0.f);
#pragma unroll 8
        for (int jj = 0; jj < 32; ++jj) {
            const int j = g * 32 + jj;
            const float4 w4 = *reinterpret_cast<const float4*>(
                &Wn[(size_t)j * FEA + 4 * q]);
            const float x = in_row[j];
            acc4.x += x * w4.x; acc4.y += x * w4.y;
            acc4.z += x * w4.z; acc4.w += x * w4.w;
        }
        *reinterpret_cast<float4*>(&partf[g][4 * q]) = acc4;
        __syncthreads();
        s_vec[t] = partf[0][t] + partf[1][t] + partf[2][t] + partf[3][t];
        __syncthreads();
    }

    // ---- phase 2: out1[j] = sum_k R[j,k] * s[k]
    const int w = t >> 5;
    const int l = t & 31;
    const float4 s4 = *reinterpret_cast<const float4*>(&s_vec[4 * l]);
    const float* __restrict__ Rn = rel + (size_t)n * FEA * FEA;

#pragma unroll 4
    for (int jj = 0; jj < 32; ++jj) {
        const int j = w * 32 + jj;
        const float4 r4 = *reinterpret_cast<const float4*>(&Rn[(size_t)j * FEA + 4 * l]);
        float p = r4.x * s4.x + r4.y * s4.y + r4.z * s4.z + r4.w * s4.w;
#pragma unroll
        for (int off = 16; off > 0; off >>= 1)
            p += __shfl_xor_sync(0xffffffffu, p, off);
        if (l == jj) {
            const __half h = __float2half_rn(p);
            const float  r = p - __half2float(h);
            g_b_hi[(size_t)j * N_NODES + n] = h;
            g_b_lo[(size_t)j * N_NODES + n] = __float2half_rn(r);
        }
    }
}

// ---------------------------------------------------------------------------
// Kernel 2: split-K HMMA GEMM.  partial[s] = adj[:, sK:(s+1)K] @ out1[sK:..]
// CTA tile 128x128, BK=64, double-buffered smem, 16 warps (4M x 4N),
// 512 threads for latency hiding (4 warps/SMSP).
// adj as single fp16 (rel err 2^-11), out1 as fp16 hi/lo -> 2 MMA per frag.
// ---------------------------------------------------------------------------
#define TILE_B 16384                        // one operand tile: 128 x 64 fp16
#define BUF_B (3 * TILE_B)                  // A, B_hi, B_lo
#define SMEM_REQ (2 * BUF_B + 1024)

__global__ __launch_bounds__(512, 1) void hmma_gemm_kernel(const float* __restrict__ A)
{
    extern __shared__ char dsm[];
    const uint32_t raw  = smem_u32(dsm);
    const uint32_t base = (raw + 1023u) & ~1023u;
    char* smb = dsm + (base - raw);

    const int t   = threadIdx.x;
    const int wid = t >> 5;
    const int l   = t & 31;
    const int m0  = blockIdx.x * 128;
    const int kb0 = blockIdx.y * KSPL;

    const int warpM = wid & 3;   // 0..3 -> 32 rows each
    const int warpN = wid >> 2;  // 0..3 -> 32 cols each

    // ---- per-lane ldmatrix address components ----
    uint32_t aRowOff[2], aXor[2];
#pragma unroll
    for (int mf = 0; mf < 2; ++mf) {
        const int r = warpM * 32 + mf * 16 + (l & 15);
        aRowOff[mf] = r * 128;
        aXor[mf]    = (r & 7) * 16;
    }
    const uint32_t aK = (l >> 4) * 16;
    uint32_t bRowOff[2], bXor[2];
#pragma unroll
    for (int q = 0; q < 2; ++q) {
        const int r = warpN * 32 + q * 16 + ((l >> 4) << 3) + (l & 7);
        bRowOff[q] = r * 128;
        bXor[q]    = (r & 7) * 16;
    }
    const uint32_t bK = ((l >> 3) & 1) * 16;

    // ---- staging maps (512 threads) ----
    const int aRow = t >> 2;                 // A: 128 rows, 4 threads/row
    const int aC4  = (t & 3) * 4;            // float4 idx, 4 per thread
    const int bRow = t >> 2;                 // B: 128 rows, 4 threads/row
    const int bC   = (t & 3) * 2;            // 16B chunk idx, 2 per thread

    float c[2][4][4];
#pragma unroll
    for (int i = 0; i < 2; ++i)
#pragma unroll
        for (int j = 0; j < 4; ++j)
#pragma unroll
            for (int k = 0; k < 4; ++k) c[i][j][k] = 0.0f;

    float4 aPre[4];

    // convert aPre -> single fp16 A tile at smem byte offset `dst`
    auto convert_store = [&](uint32_t dst) {
#pragma unroll
        for (int r = 0; r < 4; ++r) {
            const float4 v = aPre[r];
            uint2 hv;
            hv.x = h2_pack(__float2half_rn(v.x), __float2half_rn(v.y));
            hv.y = h2_pack(__float2half_rn(v.z), __float2half_rn(v.w));
            const uint32_t off = SWZ(aRow * 128 + (aC4 + r) * 8);
            *reinterpret_cast<uint2*>(smb + dst + off) = hv;
        }
    };

    // one k16 compute step on buffer at byte offset `cur`
    auto compute_step = [&](uint32_t cur, int st) {
        const uint32_t aB  = base + cur;
        const uint32_t bHb = aB + TILE_B;
        const uint32_t bLb = aB + 2 * TILE_B;
        const uint32_t k2 = st * 32;
        uint32_t ah[2][4];
#pragma unroll
        for (int mf = 0; mf < 2; ++mf)
            ldsm4(ah[mf], aB + aRowOff[mf] + ((aK + k2) ^ aXor[mf]));
        uint32_t bh[2][4], bl[2][4];
#pragma unroll
        for (int q = 0; q < 2; ++q) {
            const uint32_t off = bRowOff[q] + ((bK + k2) ^ bXor[q]);
            ldsm4(bh[q], bHb + off);
            ldsm4(bl[q], bLb + off);
        }
#pragma unroll
        for (int mf = 0; mf < 2; ++mf)
#pragma unroll
            for (int q = 0; q < 2; ++q)
#pragma unroll
                for (int h = 0; h < 2; ++h) {
                    float* cc = c[mf][2 * q + h];
                    mma16816(cc, ah[mf], &bh[q][2 * h]);
                    mma16816(cc, ah[mf], &bl[q][2 * h]);
                }
    };

    // ================== prologue: stage tile 0 into buffer 0 =================
    {
#pragma unroll
        for (int r = 0; r < 2; ++r) {
            const uint32_t dof = SWZ(bRow * 128 + (bC + r) * 16);
            const size_t   src = (size_t)bRow * KD + kb0 + (bC + r) * 8;
            cp16(base + TILE_B + dof, &g_b_hi[src]);
            cp16(base + 2 * TILE_B + dof, &g_b_lo[src]);
        }
        cp_commit();
#pragma unroll
        for (int r = 0; r < 4; ++r)
            aPre[r] = *reinterpret_cast<const float4*>(
                &A[(size_t)(m0 + aRow) * KD + kb0 + ((aC4 + r) << 2)]);
        convert_store(0);
        cp_wait0();
        __syncthreads();
    }

    // ================== main loop =============================================
    for (int kt = 0; kt < TILES; ++kt) {
        const uint32_t cur = (kt & 1) * BUF_B;
        const uint32_t nxt = cur ^ BUF_B;
        const bool have_next = (kt + 1) < TILES;

        if (have_next) {
            const int kb = kb0 + (kt + 1) * BK;
#pragma unroll
            for (int r = 0; r < 2; ++r) {
                const uint32_t dof = SWZ(bRow * 128 + (bC + r) * 16);
                const size_t   src = (size_t)bRow * KD + kb + (bC + r) * 8;
                cp16(base + nxt + TILE_B + dof, &g_b_hi[src]);
                cp16(base + nxt + 2 * TILE_B + dof, &g_b_lo[src]);
            }
            cp_commit();
#pragma unroll
            for (int r = 0; r < 4; ++r)
                aPre[r] = *reinterpret_cast<const float4*>(
                    &A[(size_t)(m0 + aRow) * KD + kb + ((aC4 + r) << 2)]);
        }

        compute_step(cur, 0);
        compute_step(cur, 1);
        if (have_next) convert_store(nxt);   // overlapped with MMA halves
        compute_step(cur, 2);
        compute_step(cur, 3);

        if (have_next) {
            cp_wait0();
            __syncthreads();
        }
    }

    // ---- epilogue: plain coalesced fp32 partial stores ----
    float* __restrict__ part = g_part[blockIdx.y];
    const int cRow = (l >> 2);
    const int cCol = (l & 3) * 2;
#pragma unroll
    for (int mf = 0; mf < 2; ++mf) {
        const int rbase = m0 + warpM * 32 + mf * 16 + cRow;
#pragma unroll
        for (int nf = 0; nf < 4; ++nf) {
            const int col = warpN * 32 + nf * 8 + cCol;
            float2 v0; v0.x = c[mf][nf][0]; v0.y = c[mf][nf][1];
            float2 v1; v1.x = c[mf][nf][2]; v1.y = c[mf][nf][3];
            *reinterpret_cast<float2*>(&part[(size_t)rbase * FEA + col])       = v0;
            *reinterpret_cast<float2*>(&part[(size_t)(rbase + 8) * FEA + col]) = v1;
        }
    }
}

// ---------------------------------------------------------------------------
// Kernel 3: sum 4 split-K partials + bias.
// ---------------------------------------------------------------------------
__global__ __launch_bounds__(256) void reduce_kernel(
    const float* __restrict__ bias, float* __restrict__ out)
{
    const int i = blockIdx.x * 256 + threadIdx.x;  // float4 index
    const float4 a = reinterpret_cast<const float4*>(g_part[0])[i];
    const float4 b = reinterpret_cast<const float4*>(g_part[1])[i];
    const float4 c = reinterpret_cast<const float4*>(g_part[2])[i];
    const float4 d = reinterpret_cast<const float4*>(g_part[3])[i];
    const float4 bi = *reinterpret_cast<const float4*>(&bias[(i & 31) << 2]);
    float4 o;
    o.x = a.x + b.x + c.x + d.x + bi.x;
    o.y = a.y + b.y + c.y + d.y + bi.y;
    o.z = a.z + b.z + c.z + d.z + bi.z;
    o.w = a.w + b.w + c.w + d.w + bi.w;
    reinterpret_cast<float4*>(out)[i] = o;
}

extern "C" void kernel_launch(void* const* d_in, const int* in_sizes, int n_in,
                              void* d_out, int out_size)
{
    const float* input = (const float*)d_in[0];  // [4096, 128]
    const float* adj   = (const float*)d_in[1];  // [4096, 4096]
    const float* rel   = (const float*)d_in[2];  // [4096, 128, 128]
    const float* W     = (const float*)d_in[3];  // [4096, 128, 128]
    const float* bias  = (const float*)d_in[4];  // [128]
    float* out = (float*)d_out;                  // [4096, 128]

    cudaFuncSetAttribute(hmma_gemm_kernel,
                         cudaFuncAttributeMaxDynamicSharedMemorySize, SMEM_REQ);

    node_transform_kernel<<<N_NODES, 128>>>(input, rel, W);
    hmma_gemm_kernel<<<dim3(32, SPLITS), 512, SMEM_REQ>>>(adj);
    reduce_kernel<<<(N_NODES * FEA / 4) / 256, 256>>>(bias, out);
}